// round 4
// baseline (speedup 1.0000x reference)
#include <cuda_runtime.h>
#include <cstdint>

// Problem constants
#define NEURONS  512
#define CHANNELS 384
#define HWSZ     169            // 13*13
#define BATCH    512
#define K_TOTAL  (CHANNELS * HWSZ)   // 64896

// GEMM tiling
#define SPLITS 16
#define KC (K_TOTAL / SPLITS)   // 4056, divisible by BK
#define BK 8
#define BM 128
#define BN 128

// Scratch (allocation-free rule: __device__ globals)
__device__ float g_W[(size_t)K_TOTAL * NEURONS];         // [k][n], k-major
__device__ float g_part[SPLITS][BATCH * NEURONS];        // split-K partials

// ---------------------------------------------------------------------------
// Kernel 1: materialize rank-1 weights  g_W[k*512+n] = W_d[n,c]*W_s[n,hw]
// ---------------------------------------------------------------------------
__global__ void precompute_w(const float* __restrict__ W_s,
                             const float* __restrict__ W_d) {
    const long long total = (long long)K_TOTAL * NEURONS;
    for (long long idx = blockIdx.x * (long long)blockDim.x + threadIdx.x;
         idx < total;
         idx += (long long)gridDim.x * blockDim.x) {
        int k  = (int)(idx >> 9);       // NEURONS == 512
        int n  = (int)(idx & 511);
        int c  = k / HWSZ;
        int hw = k - c * HWSZ;
        g_W[idx] = W_d[n * CHANNELS + c] * W_s[n * HWSZ + hw];
    }
}

// ---------------------------------------------------------------------------
// Kernel 2: split-K SGEMM  out_part[s] += x[128b x K] @ g_W[K x 128n]
// Inner loop uses packed fma.rn.f32x2 (2 fp32 FMAs per instruction — full-rate
// fp32 on sm_103a, vs half-rate 3-reg FFMA).
// ---------------------------------------------------------------------------
#define FMA2(d, a, b) asm("fma.rn.f32x2 %0, %1, %2, %0;" : "+l"(d) : "l"(a), "l"(b))
#define PACK2(o, x)   asm("mov.b64 %0, {%1, %1};" : "=l"(o) : "r"(x))

__global__ __launch_bounds__(256, 2)
void gemm_splitk(const float* __restrict__ x) {
    __shared__ __align__(16) float As[BK][BM];   // [k][b]
    __shared__ __align__(16) float Bs[BK][BN];   // [k][n]

    const int tid = threadIdx.x;
    const int bx  = blockIdx.x;   // n tile: 0..3
    const int by  = blockIdx.y;   // b tile: 0..3
    const int s   = blockIdx.z;   // K split: 0..15
    const int k0  = s * KC;

    // A-tile load mapping: 128 rows x 8 k, one float4 per thread
    const int a_row = tid >> 1;            // 0..127
    const int a_kc  = (tid & 1) * 4;       // 0 or 4
    const float* a_ptr = x + (size_t)(by * BM + a_row) * K_TOTAL + k0 + a_kc;

    // B-tile load mapping: 8 k-rows x 128 n, one float4 per thread (coalesced)
    const int b_kr  = tid >> 5;            // 0..7
    const int b_col = (tid & 31) * 4;
    const float* b_ptr = g_W + (size_t)(k0 + b_kr) * NEURONS + bx * BN + b_col;

    const int tx = tid & 15;   // n micro-tile
    const int ty = tid >> 4;   // b micro-tile

    uint64_t acc[8][4];        // 8 b-rows x 8 n-cols as 4 f32x2 pairs
    #pragma unroll
    for (int i = 0; i < 8; i++)
        #pragma unroll
        for (int j = 0; j < 4; j++) acc[i][j] = 0ull;

    // stage 0 prefetch
    float4 a_reg = *(const float4*)a_ptr;
    float4 b_reg = *(const float4*)b_ptr;

    const int NSTEPS = KC / BK;   // 507
    for (int step = 0; step < NSTEPS; ++step) {
        // commit staged tile to smem
        As[a_kc + 0][a_row] = a_reg.x;
        As[a_kc + 1][a_row] = a_reg.y;
        As[a_kc + 2][a_row] = a_reg.z;
        As[a_kc + 3][a_row] = a_reg.w;
        *(float4*)&Bs[b_kr][b_col] = b_reg;
        __syncthreads();

        // prefetch next tile while computing on this one
        if (step + 1 < NSTEPS) {
            a_ptr += BK;
            b_ptr += (size_t)BK * NEURONS;
            a_reg = *(const float4*)a_ptr;
            b_reg = *(const float4*)b_ptr;
        }

        #pragma unroll
        for (int kk = 0; kk < BK; ++kk) {
            float4 a0 = *(const float4*)&As[kk][ty * 8];
            float4 a1 = *(const float4*)&As[kk][ty * 8 + 4];
            ulonglong2 bq0 = *(const ulonglong2*)&Bs[kk][tx * 8];
            ulonglong2 bq1 = *(const ulonglong2*)&Bs[kk][tx * 8 + 4];
            uint64_t bp[4] = {bq0.x, bq0.y, bq1.x, bq1.y};
            float av[8] = {a0.x, a0.y, a0.z, a0.w, a1.x, a1.y, a1.z, a1.w};
            #pragma unroll
            for (int i = 0; i < 8; i++) {
                uint64_t a2;
                PACK2(a2, __float_as_uint(av[i]));
                #pragma unroll
                for (int j = 0; j < 4; j++) FMA2(acc[i][j], a2, bp[j]);
            }
        }
        __syncthreads();
    }

    // epilogue: write this split's 128x128 tile (16B stores, coalesced)
    float* dst = g_part[s] + (size_t)(by * BM + ty * 8) * NEURONS + bx * BN + tx * 8;
    #pragma unroll
    for (int i = 0; i < 8; i++) {
        *(ulonglong2*)(dst + (size_t)i * NEURONS)     = make_ulonglong2(acc[i][0], acc[i][1]);
        *(ulonglong2*)(dst + (size_t)i * NEURONS + 4) = make_ulonglong2(acc[i][2], acc[i][3]);
    }
}

// ---------------------------------------------------------------------------
// Kernel 3: reduce split-K partials + bias
// ---------------------------------------------------------------------------
__global__ void reduce_out(const float* __restrict__ W_b,
                           float* __restrict__ out) {
    int idx = blockIdx.x * blockDim.x + threadIdx.x;  // 0..262143 == b*512+n
    int n = idx & 511;
    float acc = W_b[n];
    #pragma unroll
    for (int s = 0; s < SPLITS; s++) acc += g_part[s][idx];
    out[idx] = acc;
}

// ---------------------------------------------------------------------------
// Entry point
// ---------------------------------------------------------------------------
extern "C" void kernel_launch(void* const* d_in, const int* in_sizes, int n_in,
                              void* d_out, int out_size) {
    const float* x   = (const float*)d_in[0];   // [512, 384, 13, 13]
    const float* W_s = (const float*)d_in[1];   // [512, 13, 13]
    const float* W_d = (const float*)d_in[2];   // [512, 384]
    const float* W_b = (const float*)d_in[3];   // [1, 512]
    float* out = (float*)d_out;                 // [512, 512]

    precompute_w<<<4096, 256>>>(W_s, W_d);

    dim3 grid(NEURONS / BN, BATCH / BM, SPLITS);  // 4 x 4 x 16 = 256 blocks
    gemm_splitk<<<grid, 256>>>(x);

    reduce_out<<<(BATCH * NEURONS) / 256, 256>>>(W_b, out);
}

// round 6
// speedup vs baseline: 4.3020x; 4.3020x over previous
#include <cuda_runtime.h>
#include <cstdint>

// ---------------------------------------------------------------------------
// Problem constants
// ---------------------------------------------------------------------------
#define NEURONS  512
#define CHANNELS 384
#define HWSZ     169
#define BATCH    512
#define K_TOTAL  (CHANNELS * HWSZ)      // 64896

// GEMM tiling: out[512,512] = x[512,K] @ W^T,  W[n,k] = W_d[n,c]*W_s[n,hw]
#define BM 128
#define BN 128
#define BKF 32                           // k floats per tile (128 B row)
#define KSTEPS_TOTAL (K_TOTAL / BKF)     // 2028
#define SPLITS 18                        // uneven: 12 splits of 113, 6 of 112
#define STAGES 3

#define A_BYTES (BM * 128)               // 16 KB
#define B_BYTES (BN * 128)               // 16 KB
#define STAGE_BYTES (A_BYTES + B_BYTES)  // 32 KB
#define SMEM_TOTAL (STAGES * STAGE_BYTES)// 96 KB

// Scratch (__device__ globals per allocation rules)
__device__ float g_W[(size_t)NEURONS * K_TOTAL];     // [n][k], tf32 values
__device__ float g_part[SPLITS][BATCH * NEURONS];    // split-K partials

// ---------------------------------------------------------------------------
// Helpers (all baseline PTX: sm_80-class, no 'a' features)
// ---------------------------------------------------------------------------
__device__ __forceinline__ uint32_t s2u(const void* p) {
    return (uint32_t)__cvta_generic_to_shared(p);
}

// 32B-granular swizzle: 16B chunk c (0..7) of row r ->
// off = r*128 + ((c>>1 ^ (r&3))<<5) + (c&1)*16
__device__ __forceinline__ uint32_t tile_off(uint32_t row, uint32_t c16) {
    return row * 128u + ((((c16 >> 1) ^ (row & 3u)) << 5)) + ((c16 & 1u) << 4);
}

#define CPA16(dst, src) \
    asm volatile("cp.async.cg.shared.global [%0], [%1], 16;" :: "r"(dst), "l"(src))
#define CP_COMMIT()  asm volatile("cp.async.commit_group;" ::: "memory")
#define CP_WAIT(n)   asm volatile("cp.async.wait_group %0;" :: "n"(n) : "memory")

#define LDSM_X4(r0, r1, r2, r3, a) \
    asm volatile("ldmatrix.sync.aligned.m8n8.x4.shared.b16 {%0,%1,%2,%3}, [%4];" \
                 : "=r"(r0), "=r"(r1), "=r"(r2), "=r"(r3) : "r"(a))

#define MMA_TF32(c, a, b0, b1) \
    asm volatile("mma.sync.aligned.m16n8k8.row.col.f32.tf32.tf32.f32 " \
                 "{%0,%1,%2,%3},{%4,%5,%6,%7},{%8,%9},{%0,%1,%2,%3};" \
                 : "+f"((c)[0]), "+f"((c)[1]), "+f"((c)[2]), "+f"((c)[3]) \
                 : "r"((a)[0]), "r"((a)[1]), "r"((a)[2]), "r"((a)[3]), \
                   "r"(b0), "r"(b1))

__device__ __forceinline__ uint32_t cvt_rna_tf32(uint32_t x) {
    uint32_t r;
    asm("cvt.rna.tf32.f32 %0, %1;" : "=r"(r) : "f"(__uint_as_float(x)));
    return r;
}

// ---------------------------------------------------------------------------
// Kernel 1: g_W[n][k] = rna_tf32(W_d[n,c] * W_s[n,hw]); one block per neuron
// ---------------------------------------------------------------------------
__global__ void __launch_bounds__(256) precompute_w(const float* __restrict__ W_s,
                                                    const float* __restrict__ W_d) {
    const int n = blockIdx.x;
    __shared__ float ws[HWSZ];
    __shared__ float wd[CHANNELS];
    for (int i = threadIdx.x; i < HWSZ; i += 256)     ws[i] = W_s[n * HWSZ + i];
    for (int i = threadIdx.x; i < CHANNELS; i += 256) wd[i] = W_d[n * CHANNELS + i];
    __syncthreads();
    float* dst = g_W + (size_t)n * K_TOTAL;
    for (int k = threadIdx.x; k < K_TOTAL; k += 256) {
        int c  = k / HWSZ;                 // constant divisor -> mul-hi
        int hw = k - c * HWSZ;
        float v = wd[c] * ws[hw];
        uint32_t u;
        asm("cvt.rna.tf32.f32 %0, %1;" : "=r"(u) : "f"(v));
        dst[k] = __uint_as_float(u);
    }
}

// ---------------------------------------------------------------------------
// Kernel 2: tf32 mma.sync split-K GEMM (sm80-style 3-stage cp.async pipeline)
// 256 threads = 8 warps, warp tile 64x32, CTA tile 128x128x32f.
// ---------------------------------------------------------------------------
__global__ void __launch_bounds__(256, 2) gemm_tf32(const float* __restrict__ x) {
    extern __shared__ char smem[];
    const uint32_t sbase = s2u(smem);

    const int tid  = threadIdx.x;
    const int wid  = tid >> 5;
    const int lane = tid & 31;
    const int n0 = blockIdx.x * BN;
    const int m0 = blockIdx.y * BM;
    const int s  = blockIdx.z;

    // uneven split-K: first 12 splits get 113 k-steps, rest 112
    const int NT  = 112 + (s < 12 ? 1 : 0);
    const int ks0 = 112 * s + (s < 12 ? s : 12);

    const float* xbase = x   + (size_t)m0 * K_TOTAL + (size_t)ks0 * BKF;
    const float* wbase = g_W + (size_t)n0 * K_TOTAL + (size_t)ks0 * BKF;

    // warp tile position
    const int wm = (wid & 1) * 64;        // 0 or 64
    const int wn = (wid >> 1) * 32;       // 0,32,64,96

    // ldmatrix per-lane row/chunk pieces
    const int sub = lane >> 3;            // 0..3 (matrix index)
    const int r8  = lane & 7;

    float acc[4][4][4];                   // [mtile][ntile][frag]
    #pragma unroll
    for (int i = 0; i < 4; i++)
        #pragma unroll
        for (int j = 0; j < 4; j++)
            #pragma unroll
            for (int f = 0; f < 4; f++) acc[i][j][f] = 0.f;

    // ---- stage fill: 2048 16B chunks (A:1024, B:1024), 8 per thread -------
    auto fill = [&](int t) {
        const uint32_t sa = sbase + (t % STAGES) * STAGE_BYTES;
        const uint32_t sB = sa + A_BYTES;
        const float* xs = xbase + (size_t)t * BKF;
        const float* ws = wbase + (size_t)t * BKF;
        #pragma unroll
        for (int i = 0; i < 4; i++) {
            int slot = tid + i * 256;     // 0..1023
            uint32_t row = slot >> 3, c = slot & 7;
            uint32_t off = tile_off(row, c);
            CPA16(sa + off, xs + (size_t)row * K_TOTAL + c * 4);
            CPA16(sB + off, ws + (size_t)row * K_TOTAL + c * 4);
        }
        CP_COMMIT();
    };

    fill(0);
    fill(1);

    for (int t = 0; t < NT; t++) {
        CP_WAIT(1);                        // stage t%3 resident
        __syncthreads();

        if (t + 2 < NT) fill(t + 2);       // overwrites stage (t-1)%3 (safe: sync above)

        const uint32_t sa = sbase + (t % STAGES) * STAGE_BYTES;
        const uint32_t sB = sa + A_BYTES;

        #pragma unroll
        for (int ks = 0; ks < 4; ks++) {
            // A fragments: 4 m16 tiles, ldmatrix.x4.b16 each
            uint32_t a[4][4];
            #pragma unroll
            for (int i = 0; i < 4; i++) {
                uint32_t row = wm + i * 16 + (sub & 1) * 8 + r8;
                uint32_t addr = sa + row * 128 +
                                (((uint32_t)ks ^ (row & 3u)) << 5) + ((sub >> 1) << 4);
                LDSM_X4(a[i][0], a[i][1], a[i][2], a[i][3], addr);
                a[i][0] = cvt_rna_tf32(a[i][0]);
                a[i][1] = cvt_rna_tf32(a[i][1]);
                a[i][2] = cvt_rna_tf32(a[i][2]);
                a[i][3] = cvt_rna_tf32(a[i][3]);
            }
            // B fragments: 2 n16 groups (4 n8 tiles); g_W already tf32
            uint32_t b[2][4];
            #pragma unroll
            for (int p = 0; p < 2; p++) {
                uint32_t row = wn + p * 16 + (sub >> 1) * 8 + r8;
                uint32_t addr = sB + row * 128 +
                                (((uint32_t)ks ^ (row & 3u)) << 5) + ((sub & 1) << 4);
                LDSM_X4(b[p][0], b[p][1], b[p][2], b[p][3], addr);
            }
            #pragma unroll
            for (int i = 0; i < 4; i++)
                #pragma unroll
                for (int j = 0; j < 4; j++)
                    MMA_TF32(acc[i][j], a[i], b[j >> 1][(j & 1) * 2],
                             b[j >> 1][(j & 1) * 2 + 1]);
        }
        __syncthreads();
    }

    // ---- epilogue: write split partial tile ---------------------------------
    const int g  = lane >> 2;
    const int t4 = lane & 3;
    float* base = g_part[s];
    #pragma unroll
    for (int i = 0; i < 4; i++) {
        #pragma unroll
        for (int j = 0; j < 4; j++) {
            int row = m0 + wm + i * 16 + g;
            int col = n0 + wn + j * 8 + t4 * 2;
            *(float2*)&base[(size_t)row * NEURONS + col] =
                make_float2(acc[i][j][0], acc[i][j][1]);
            *(float2*)&base[(size_t)(row + 8) * NEURONS + col] =
                make_float2(acc[i][j][2], acc[i][j][3]);
        }
    }
}

// ---------------------------------------------------------------------------
// Kernel 3: sum split-K partials + bias (float4)
// ---------------------------------------------------------------------------
__global__ void __launch_bounds__(256) reduce_out(const float* __restrict__ W_b,
                                                  float* __restrict__ out) {
    int i4 = blockIdx.x * blockDim.x + threadIdx.x;   // 65536 float4 slots
    int n4 = i4 & (NEURONS / 4 - 1);
    float4 a = ((const float4*)W_b)[n4];
    #pragma unroll
    for (int sp = 0; sp < SPLITS; sp++) {
        float4 p = *(const float4*)&g_part[sp][(size_t)i4 * 4];
        a.x += p.x; a.y += p.y; a.z += p.z; a.w += p.w;
    }
    ((float4*)out)[i4] = a;
}

// ---------------------------------------------------------------------------
// Entry point
// ---------------------------------------------------------------------------
extern "C" void kernel_launch(void* const* d_in, const int* in_sizes, int n_in,
                              void* d_out, int out_size) {
    const float* x   = (const float*)d_in[0];   // [512, 384, 13, 13]
    const float* W_s = (const float*)d_in[1];   // [512, 13, 13]
    const float* W_d = (const float*)d_in[2];   // [512, 384]
    const float* W_b = (const float*)d_in[3];   // [1, 512]
    float* out = (float*)d_out;                 // [512, 512]

    (void)cudaFuncSetAttribute(gemm_tf32,
        cudaFuncAttributeMaxDynamicSharedMemorySize, SMEM_TOTAL);

    precompute_w<<<NEURONS, 256>>>(W_s, W_d);

    dim3 grid(NEURONS / BN, BATCH / BM, SPLITS);   // 4 x 4 x 18 = 288 CTAs
    gemm_tf32<<<grid, 256, SMEM_TOTAL>>>(x);

    reduce_out<<<(BATCH * NEURONS) / (256 * 4), 256>>>(W_b, out);
}